// round 8
// baseline (speedup 1.0000x reference)
#include <cuda_runtime.h>
#include <cuda_bf16.h>
#include <cstdint>

// ---------------------------------------------------------------------------
// SpikeLinear: out = x @ W^T + bias, then LIF scan (T=16), fully fused.
//
// Round 8: BK=32 (32 iterations/block instead of 64) to halve the
// __syncthreads count; each barrier drains the FFMA2 pipe while the slowest
// warp finishes its dependent chain (~300 cyc/iter ~ the measured 6% gap to
// the rt=3 FFMA2 floor). Arithmetic is bitwise-identical to rounds 4-7
// (Eigen kc=248 panel replication via fma.rn.f32x2, rel_err 0.000970705):
// ascending-k fmaf per panel, ascending panel folds (k_end = 248/496/744/
// 992/1024), + bias, ascending-t LIF scan.
// ---------------------------------------------------------------------------

#define KC 248               // Eigen panel width (validated round 4)

#define BM 128
#define BN 64
#define BK 32
#define TM 8                 // m rows per thread (4 packed pairs)
#define TN 4                 // n cols per thread
#define T_STEPS 16

#define FMA_F32X2(d, a, b, c) \
    asm("fma.rn.f32x2 %0, %1, %2, %3;" : "=l"(d) : "l"(a), "l"(b), "l"(c))
#define ADD_F32X2_(d, a, b) \
    asm("add.rn.f32x2 %0, %1, %2;" : "=l"(d) : "l"(a), "l"(b))
#define PACK_DUP_F32(d, x) \
    asm("mov.b64 %0, {%1, %2};" : "=l"(d) : "f"(x), "f"(x))
#define UNPACK_F32X2_(lo, hi, p) \
    asm("mov.b64 {%0, %1}, %2;" : "=f"(lo), "=f"(hi) : "l"(p))

__global__ __launch_bounds__(256, 2)
void spikelinear_fused_kernel(const float* __restrict__ A,
                              const float* __restrict__ W,
                              const float* __restrict__ bias,
                              float* __restrict__ spikes,
                              int B, int N, int K) {
    __shared__ float As[2][BK][BM];   // 32 KB
    __shared__ float Ws[2][BK][BN];   // 16 KB   (total 48 KB = static max)

    const int tid    = threadIdx.x;          // 0..255
    const int b_tile = blockIdx.y;            // batch tile (8 b's)
    const int bcol   = blockIdx.x;            // N tile

    const int tcol = tid % (BN / TN);          // 0..15
    const int trow = tid / (BN / TN);          // 0..15

    const int b_base = b_tile * (BM / T_STEPS);   // 8 b's per block

    // packed accumulators: [m-pair 0..3][n 0..3]
    unsigned long long cur[4][TN];
    unsigned long long tot[4][TN];
    #pragma unroll
    for (int i = 0; i < 4; i++)
        #pragma unroll
        for (int j = 0; j < TN; j++) { cur[i][j] = 0ull; tot[i][j] = 0ull; }

    const float* Wb = W + (size_t)bcol * BN * K;

    // loader mapping (BK=32): A tile 128x32 = 1024 float4 -> 4/thread,
    // W tile 64x32 = 512 float4 -> 2/thread.
    const int ld_row = tid / 8;               // 0..31
    const int ld_col = (tid % 8) * 4;         // 0,4,...,28

    // tile_row -> global m:  b_local = row>>4, t = row&15, m = t*B + b_base + b_local
    const int ar0 = ld_row;
    const int ar1 = ld_row + 32;
    const int ar2 = ld_row + 64;
    const int ar3 = ld_row + 96;
    const float* rowA0 = A + (size_t)((ar0 & 15) * B + b_base + (ar0 >> 4)) * K;
    const float* rowA1 = A + (size_t)((ar1 & 15) * B + b_base + (ar1 >> 4)) * K;
    const float* rowA2 = A + (size_t)((ar2 & 15) * B + b_base + (ar2 >> 4)) * K;
    const float* rowA3 = A + (size_t)((ar3 & 15) * B + b_base + (ar3 >> 4)) * K;
    const float* rowW0 = Wb + (size_t)ld_row * K;
    const float* rowW1 = Wb + (size_t)(ld_row + 32) * K;

    float4 rA0, rA1, rA2, rA3, rW0, rW1;

    // ---- prologue: load tile 0 ----
    rA0 = *reinterpret_cast<const float4*>(rowA0 + ld_col);
    rA1 = *reinterpret_cast<const float4*>(rowA1 + ld_col);
    rA2 = *reinterpret_cast<const float4*>(rowA2 + ld_col);
    rA3 = *reinterpret_cast<const float4*>(rowA3 + ld_col);
    rW0 = *reinterpret_cast<const float4*>(rowW0 + ld_col);
    rW1 = *reinterpret_cast<const float4*>(rowW1 + ld_col);
    {
        As[0][ld_col + 0][ar0] = rA0.x;  As[0][ld_col + 1][ar0] = rA0.y;
        As[0][ld_col + 2][ar0] = rA0.z;  As[0][ld_col + 3][ar0] = rA0.w;
        As[0][ld_col + 0][ar1] = rA1.x;  As[0][ld_col + 1][ar1] = rA1.y;
        As[0][ld_col + 2][ar1] = rA1.z;  As[0][ld_col + 3][ar1] = rA1.w;
        As[0][ld_col + 0][ar2] = rA2.x;  As[0][ld_col + 1][ar2] = rA2.y;
        As[0][ld_col + 2][ar2] = rA2.z;  As[0][ld_col + 3][ar2] = rA2.w;
        As[0][ld_col + 0][ar3] = rA3.x;  As[0][ld_col + 1][ar3] = rA3.y;
        As[0][ld_col + 2][ar3] = rA3.z;  As[0][ld_col + 3][ar3] = rA3.w;
        Ws[0][ld_col + 0][ld_row]      = rW0.x;  Ws[0][ld_col + 1][ld_row]      = rW0.y;
        Ws[0][ld_col + 2][ld_row]      = rW0.z;  Ws[0][ld_col + 3][ld_row]      = rW0.w;
        Ws[0][ld_col + 0][ld_row + 32] = rW1.x;  Ws[0][ld_col + 1][ld_row + 32] = rW1.y;
        Ws[0][ld_col + 2][ld_row + 32] = rW1.z;  Ws[0][ld_col + 3][ld_row + 32] = rW1.w;
    }
    __syncthreads();

    int buf = 0;
    for (int k0 = 0; k0 < K; k0 += BK) {
        const bool has_next = (k0 + BK < K);

        if (has_next) {
            const int kn = k0 + BK + ld_col;
            rA0 = *reinterpret_cast<const float4*>(rowA0 + kn);
            rA1 = *reinterpret_cast<const float4*>(rowA1 + kn);
            rA2 = *reinterpret_cast<const float4*>(rowA2 + kn);
            rA3 = *reinterpret_cast<const float4*>(rowA3 + kn);
            rW0 = *reinterpret_cast<const float4*>(rowW0 + kn);
            rW1 = *reinterpret_cast<const float4*>(rowW1 + kn);
        }

        // Eigen fold position within this tile (at most one):
        // boundaries k_end = 248, 496, 744, 992 (locals 23,15,7,31) and K.
        int fold_local = -1;
        {
            int next_b = ((k0 / KC) + 1) * KC;
            if (next_b <= k0 + BK)      fold_local = next_b - k0 - 1;
            else if (k0 + BK == K)      fold_local = BK - 1;
        }

        #pragma unroll
        for (int k = 0; k < BK; k++) {
            const ulonglong2* As2 =
                reinterpret_cast<const ulonglong2*>(&As[buf][k][trow * TM]);
            ulonglong2 al = As2[0];
            ulonglong2 ah = As2[1];
            unsigned long long ap[4] = {al.x, al.y, ah.x, ah.y};

            const float4* Ws4 = reinterpret_cast<const float4*>(&Ws[buf][k][0]);
            float4 w = Ws4[tcol];
            unsigned long long wp[TN];
            PACK_DUP_F32(wp[0], w.x);
            PACK_DUP_F32(wp[1], w.y);
            PACK_DUP_F32(wp[2], w.z);
            PACK_DUP_F32(wp[3], w.w);

            #pragma unroll
            for (int i = 0; i < 4; i++)
                #pragma unroll
                for (int j = 0; j < TN; j++)
                    FMA_F32X2(cur[i][j], ap[i], wp[j], cur[i][j]);

            if (k == fold_local) {
                #pragma unroll
                for (int i = 0; i < 4; i++)
                    #pragma unroll
                    for (int j = 0; j < TN; j++) {
                        ADD_F32X2_(tot[i][j], tot[i][j], cur[i][j]);
                        cur[i][j] = 0ull;
                    }
            }
        }

        if (has_next) {
            const int nb = buf ^ 1;
            As[nb][ld_col + 0][ar0] = rA0.x;  As[nb][ld_col + 1][ar0] = rA0.y;
            As[nb][ld_col + 2][ar0] = rA0.z;  As[nb][ld_col + 3][ar0] = rA0.w;
            As[nb][ld_col + 0][ar1] = rA1.x;  As[nb][ld_col + 1][ar1] = rA1.y;
            As[nb][ld_col + 2][ar1] = rA1.z;  As[nb][ld_col + 3][ar1] = rA1.w;
            As[nb][ld_col + 0][ar2] = rA2.x;  As[nb][ld_col + 1][ar2] = rA2.y;
            As[nb][ld_col + 2][ar2] = rA2.z;  As[nb][ld_col + 3][ar2] = rA2.w;
            As[nb][ld_col + 0][ar3] = rA3.x;  As[nb][ld_col + 1][ar3] = rA3.y;
            As[nb][ld_col + 2][ar3] = rA3.z;  As[nb][ld_col + 3][ar3] = rA3.w;
            Ws[nb][ld_col + 0][ld_row]      = rW0.x;  Ws[nb][ld_col + 1][ld_row]      = rW0.y;
            Ws[nb][ld_col + 2][ld_row]      = rW0.z;  Ws[nb][ld_col + 3][ld_row]      = rW0.w;
            Ws[nb][ld_col + 0][ld_row + 32] = rW1.x;  Ws[nb][ld_col + 1][ld_row + 32] = rW1.y;
            Ws[nb][ld_col + 2][ld_row + 32] = rW1.z;  Ws[nb][ld_col + 3][ld_row + 32] = rW1.w;
            __syncthreads();
            buf = nb;
        }
    }

    // ------------------------- fused epilogue -------------------------
    // thread rows: tile rows trow*8 + r (r=0..7)
    //   b_local = trow>>1, t = (trow&1)*8 + r
    const int n0 = bcol * BN + tcol * TN;
    const int b  = b_base + (trow >> 1);
    const bool upper = (trow & 1);

    // unpack + bias (identical scalar fp32 add as rounds 4-7)
    float v[8][TN];
    #pragma unroll
    for (int i = 0; i < 4; i++) {
        float lo[TN], hi[TN];
        #pragma unroll
        for (int j = 0; j < TN; j++)
            UNPACK_F32X2_(lo[j], hi[j], tot[i][j]);
        #pragma unroll
        for (int j = 0; j < TN; j++) {
            v[2 * i + 0][j] = lo[j] + bias[n0 + j];
            v[2 * i + 1][j] = hi[j] + bias[n0 + j];
        }
    }

    // LIF scan, ascending t. Pass 1: scan from 0 (valid for lower half).
    float sp[8][TN];
    float fin[TN];
    #pragma unroll
    for (int j = 0; j < TN; j++) {
        float memb = 0.0f;
        #pragma unroll
        for (int r = 0; r < 8; r++) {
            memb += v[r][j];
            float s = (memb > 1.0f) ? 1.0f : 0.0f;
            sp[r][j] = s;
            memb = (s > 0.0f) ? 0.0f : memb;
        }
        fin[j] = memb;
    }
    // hand membrane from lower half (lane l) to upper half (lane l+16)
    #pragma unroll
    for (int j = 0; j < TN; j++)
        fin[j] = __shfl_up_sync(0xffffffffu, fin[j], 16);
    if (upper) {
        #pragma unroll
        for (int j = 0; j < TN; j++) {
            float memb = fin[j];
            #pragma unroll
            for (int r = 0; r < 8; r++) {
                memb += v[r][j];
                float s = (memb > 1.0f) ? 1.0f : 0.0f;
                sp[r][j] = s;
                memb = (s > 0.0f) ? 0.0f : memb;
            }
        }
    }

    // store spikes: row m = t*B + b, t = upper*8 + r
    #pragma unroll
    for (int r = 0; r < 8; r++) {
        const int t = (upper ? 8 : 0) + r;
        float* crow = spikes + (size_t)(t * B + b) * N + n0;
        float4 o;
        o.x = sp[r][0];
        o.y = sp[r][1];
        o.z = sp[r][2];
        o.w = sp[r][3];
        *reinterpret_cast<float4*>(crow) = o;
    }
}

// ----------------------------- launch --------------------------------------
extern "C" void kernel_launch(void* const* d_in, const int* in_sizes, int n_in,
                              void* d_out, int out_size) {
    const float* x    = (const float*)d_in[0];  // [T*B, F_IN]
    const float* w    = (const float*)d_in[1];  // [F_OUT, F_IN]
    const float* bias = (const float*)d_in[2];  // [F_OUT]

    const int F_OUT = in_sizes[2];                 // 1024
    const int F_IN  = in_sizes[1] / F_OUT;         // 1024
    const int M     = in_sizes[0] / F_IN;          // 32768
    const int B     = M / T_STEPS;                 // 2048

    dim3 grid(F_OUT / BN, B / (BM / T_STEPS));     // (16, 256)
    spikelinear_fused_kernel<<<grid, 256>>>(x, w, bias, (float*)d_out,
                                            B, F_OUT, F_IN);
}

// round 9
// speedup vs baseline: 1.0037x; 1.0037x over previous
#include <cuda_runtime.h>
#include <cuda_bf16.h>
#include <cstdint>

// ---------------------------------------------------------------------------
// SpikeLinear: out = x @ W^T + bias, then LIF scan (T=16), fully fused.
//
// Round 9: BK=32 retry with the register blowup fixed. Round 8 showed BK=32
// spilled (regs=128 cap, L1 90% = local traffic). The 'tot' panel
// accumulators (32 regs, touched only at the 5 Eigen folds + epilogue) move
// to per-thread-private shared memory slots; k-loop register budget drops to
// ~95, no spills, and the halved barrier count gets a clean test.
//
// Arithmetic bitwise-identical to rounds 4-8 (Eigen kc=248 panel replication
// via fma.rn.f32x2, rel_err 0.000970705).
// ---------------------------------------------------------------------------

#define KC 248               // Eigen panel width (validated round 4)

#define BM 128
#define BN 64
#define BK 32
#define TN 4
#define T_STEPS 16
#define NACC 16              // 4 m-pairs x 4 n per thread

// dynamic smem layout (bytes)
#define AS_BYTES   (2 * BK * BM * 4)          // 32 KB
#define WS_BYTES   (2 * BK * BN * 4)          // 16 KB
#define TOT_BYTES  (NACC * 256 * 8)           // 32 KB
#define SMEM_BYTES (AS_BYTES + WS_BYTES + TOT_BYTES)   // 80 KB

#define FMA_F32X2(d, a, b, c) \
    asm("fma.rn.f32x2 %0, %1, %2, %3;" : "=l"(d) : "l"(a), "l"(b), "l"(c))
#define ADD_F32X2_(d, a, b) \
    asm("add.rn.f32x2 %0, %1, %2;" : "=l"(d) : "l"(a), "l"(b))
#define PACK_DUP_F32(d, x) \
    asm("mov.b64 %0, {%1, %2};" : "=l"(d) : "f"(x), "f"(x))
#define UNPACK_F32X2_(lo, hi, p) \
    asm("mov.b64 {%0, %1}, %2;" : "=f"(lo), "=f"(hi) : "l"(p))

__global__ __launch_bounds__(256, 2)
void spikelinear_fused_kernel(const float* __restrict__ A,
                              const float* __restrict__ W,
                              const float* __restrict__ bias,
                              float* __restrict__ spikes,
                              int B, int N, int K) {
    extern __shared__ char smem_raw[];
    float* As_s = reinterpret_cast<float*>(smem_raw);                 // [2][BK][BM]
    float* Ws_s = reinterpret_cast<float*>(smem_raw + AS_BYTES);      // [2][BK][BN]
    unsigned long long* tot_s =
        reinterpret_cast<unsigned long long*>(smem_raw + AS_BYTES + WS_BYTES); // [NACC][256]

    #define AS(b, k, m) As_s[(((b) * BK) + (k)) * BM + (m)]
    #define WS(b, k, n) Ws_s[(((b) * BK) + (k)) * BN + (n)]

    const int tid    = threadIdx.x;          // 0..255
    const int b_tile = blockIdx.y;            // batch tile (8 b's)
    const int bcol   = blockIdx.x;            // N tile

    const int tcol = tid % (BN / TN);          // 0..15
    const int trow = tid / (BN / TN);          // 0..15

    const int b_base = b_tile * (BM / T_STEPS);   // 8 b's per block

    // panel accumulator (registers); tot lives in shared
    unsigned long long cur[4][TN];
    #pragma unroll
    for (int i = 0; i < 4; i++)
        #pragma unroll
        for (int j = 0; j < TN; j++) cur[i][j] = 0ull;

    // zero the per-thread tot slots (private: no sync needed)
    #pragma unroll
    for (int idx = 0; idx < NACC; idx++)
        tot_s[idx * 256 + tid] = 0ull;

    const float* Wb = W + (size_t)bcol * BN * K;

    // loader mapping (BK=32): A tile 128x32 = 1024 float4 -> 4/thread,
    // W tile 64x32 = 512 float4 -> 2/thread.
    const int ld_row = tid / 8;               // 0..31
    const int ld_col = (tid % 8) * 4;         // 0,4,...,28

    // tile_row -> global m:  b_local = row>>4, t = row&15, m = t*B + b_base + b_local
    const int ar0 = ld_row;
    const int ar1 = ld_row + 32;
    const int ar2 = ld_row + 64;
    const int ar3 = ld_row + 96;
    const float* rowA0 = A + (size_t)((ar0 & 15) * B + b_base + (ar0 >> 4)) * K;
    const float* rowA1 = A + (size_t)((ar1 & 15) * B + b_base + (ar1 >> 4)) * K;
    const float* rowA2 = A + (size_t)((ar2 & 15) * B + b_base + (ar2 >> 4)) * K;
    const float* rowA3 = A + (size_t)((ar3 & 15) * B + b_base + (ar3 >> 4)) * K;
    const float* rowW0 = Wb + (size_t)ld_row * K;
    const float* rowW1 = Wb + (size_t)(ld_row + 32) * K;

    float4 rA0, rA1, rA2, rA3, rW0, rW1;

    // ---- prologue: load tile 0 ----
    rA0 = *reinterpret_cast<const float4*>(rowA0 + ld_col);
    rA1 = *reinterpret_cast<const float4*>(rowA1 + ld_col);
    rA2 = *reinterpret_cast<const float4*>(rowA2 + ld_col);
    rA3 = *reinterpret_cast<const float4*>(rowA3 + ld_col);
    rW0 = *reinterpret_cast<const float4*>(rowW0 + ld_col);
    rW1 = *reinterpret_cast<const float4*>(rowW1 + ld_col);
    {
        AS(0, ld_col + 0, ar0) = rA0.x;  AS(0, ld_col + 1, ar0) = rA0.y;
        AS(0, ld_col + 2, ar0) = rA0.z;  AS(0, ld_col + 3, ar0) = rA0.w;
        AS(0, ld_col + 0, ar1) = rA1.x;  AS(0, ld_col + 1, ar1) = rA1.y;
        AS(0, ld_col + 2, ar1) = rA1.z;  AS(0, ld_col + 3, ar1) = rA1.w;
        AS(0, ld_col + 0, ar2) = rA2.x;  AS(0, ld_col + 1, ar2) = rA2.y;
        AS(0, ld_col + 2, ar2) = rA2.z;  AS(0, ld_col + 3, ar2) = rA2.w;
        AS(0, ld_col + 0, ar3) = rA3.x;  AS(0, ld_col + 1, ar3) = rA3.y;
        AS(0, ld_col + 2, ar3) = rA3.z;  AS(0, ld_col + 3, ar3) = rA3.w;
        WS(0, ld_col + 0, ld_row)      = rW0.x;  WS(0, ld_col + 1, ld_row)      = rW0.y;
        WS(0, ld_col + 2, ld_row)      = rW0.z;  WS(0, ld_col + 3, ld_row)      = rW0.w;
        WS(0, ld_col + 0, ld_row + 32) = rW1.x;  WS(0, ld_col + 1, ld_row + 32) = rW1.y;
        WS(0, ld_col + 2, ld_row + 32) = rW1.z;  WS(0, ld_col + 3, ld_row + 32) = rW1.w;
    }
    __syncthreads();

    int buf = 0;
    for (int k0 = 0; k0 < K; k0 += BK) {
        const bool has_next = (k0 + BK < K);

        if (has_next) {
            const int kn = k0 + BK + ld_col;
            rA0 = *reinterpret_cast<const float4*>(rowA0 + kn);
            rA1 = *reinterpret_cast<const float4*>(rowA1 + kn);
            rA2 = *reinterpret_cast<const float4*>(rowA2 + kn);
            rA3 = *reinterpret_cast<const float4*>(rowA3 + kn);
            rW0 = *reinterpret_cast<const float4*>(rowW0 + kn);
            rW1 = *reinterpret_cast<const float4*>(rowW1 + kn);
        }

        // Eigen fold position within this tile (at most one):
        // boundaries k_end = 248, 496, 744, 992 (locals 23,15,7,31) and K.
        int fold_local = -1;
        {
            int next_b = ((k0 / KC) + 1) * KC;
            if (next_b <= k0 + BK)      fold_local = next_b - k0 - 1;
            else if (k0 + BK == K)      fold_local = BK - 1;
        }

        #pragma unroll
        for (int k = 0; k < BK; k++) {
            const ulonglong2* As2 =
                reinterpret_cast<const ulonglong2*>(&AS(buf, k, trow * 8));
            ulonglong2 al = As2[0];
            ulonglong2 ah = As2[1];
            unsigned long long ap[4] = {al.x, al.y, ah.x, ah.y};

            const float4* Ws4 = reinterpret_cast<const float4*>(&WS(buf, k, 0));
            float4 w = Ws4[tcol];
            unsigned long long wp[TN];
            PACK_DUP_F32(wp[0], w.x);
            PACK_DUP_F32(wp[1], w.y);
            PACK_DUP_F32(wp[2], w.z);
            PACK_DUP_F32(wp[3], w.w);

            #pragma unroll
            for (int i = 0; i < 4; i++)
                #pragma unroll
                for (int j = 0; j < TN; j++)
                    FMA_F32X2(cur[i][j], ap[i], wp[j], cur[i][j]);

            // Eigen panel fold: tot (in shared) += cur; cur = 0
            if (k == fold_local) {
                #pragma unroll
                for (int i = 0; i < 4; i++)
                    #pragma unroll
                    for (int j = 0; j < TN; j++) {
                        const int idx = i * TN + j;
                        unsigned long long t = tot_s[idx * 256 + tid];
                        ADD_F32X2_(t, t, cur[i][j]);
                        tot_s[idx * 256 + tid] = t;
                        cur[i][j] = 0ull;
                    }
            }
        }

        if (has_next) {
            const int nb = buf ^ 1;
            AS(nb, ld_col + 0, ar0) = rA0.x;  AS(nb, ld_col + 1, ar0) = rA0.y;
            AS(nb, ld_col + 2, ar0) = rA0.z;  AS(nb, ld_col + 3, ar0) = rA0.w;
            AS(nb, ld_col + 0, ar1) = rA1.x;  AS(nb, ld_col + 1, ar1) = rA1.y;
            AS(nb, ld_col + 2, ar1) = rA1.z;  AS(nb, ld_col + 3, ar1) = rA1.w;
            AS(nb, ld_col + 0, ar2) = rA2.x;  AS(nb, ld_col + 1, ar2) = rA2.y;
            AS(nb, ld_col + 2, ar2) = rA2.z;  AS(nb, ld_col + 3, ar2) = rA2.w;
            AS(nb, ld_col + 0, ar3) = rA3.x;  AS(nb, ld_col + 1, ar3) = rA3.y;
            AS(nb, ld_col + 2, ar3) = rA3.z;  AS(nb, ld_col + 3, ar3) = rA3.w;
            WS(nb, ld_col + 0, ld_row)      = rW0.x;  WS(nb, ld_col + 1, ld_row)      = rW0.y;
            WS(nb, ld_col + 2, ld_row)      = rW0.z;  WS(nb, ld_col + 3, ld_row)      = rW0.w;
            WS(nb, ld_col + 0, ld_row + 32) = rW1.x;  WS(nb, ld_col + 1, ld_row + 32) = rW1.y;
            WS(nb, ld_col + 2, ld_row + 32) = rW1.z;  WS(nb, ld_col + 3, ld_row + 32) = rW1.w;
            __syncthreads();
            buf = nb;
        }
    }

    // ------------------------- fused epilogue -------------------------
    // thread rows: tile rows trow*8 + r (r=0..7)
    //   b_local = trow>>1, t = (trow&1)*8 + r
    const int n0 = bcol * BN + tcol * TN;
    const int b  = b_base + (trow >> 1);
    const bool upper = (trow & 1);

    // unpack tot (from shared) + bias (identical scalar fp32 add)
    float v[8][TN];
    #pragma unroll
    for (int i = 0; i < 4; i++) {
        #pragma unroll
        for (int j = 0; j < TN; j++) {
            unsigned long long t = tot_s[(i * TN + j) * 256 + tid];
            float lo, hi;
            UNPACK_F32X2_(lo, hi, t);
            v[2 * i + 0][j] = lo + bias[n0 + j];
            v[2 * i + 1][j] = hi + bias[n0 + j];
        }
    }

    // LIF scan, ascending t. Pass 1: scan from 0 (valid for lower half).
    float sp[8][TN];
    float fin[TN];
    #pragma unroll
    for (int j = 0; j < TN; j++) {
        float memb = 0.0f;
        #pragma unroll
        for (int r = 0; r < 8; r++) {
            memb += v[r][j];
            float s = (memb > 1.0f) ? 1.0f : 0.0f;
            sp[r][j] = s;
            memb = (s > 0.0f) ? 0.0f : memb;
        }
        fin[j] = memb;
    }
    // hand membrane from lower half (lane l) to upper half (lane l+16)
    #pragma unroll
    for (int j = 0; j < TN; j++)
        fin[j] = __shfl_up_sync(0xffffffffu, fin[j], 16);
    if (upper) {
        #pragma unroll
        for (int j = 0; j < TN; j++) {
            float memb = fin[j];
            #pragma unroll
            for (int r = 0; r < 8; r++) {
                memb += v[r][j];
                float s = (memb > 1.0f) ? 1.0f : 0.0f;
                sp[r][j] = s;
                memb = (s > 0.0f) ? 0.0f : memb;
            }
        }
    }

    // store spikes: row m = t*B + b, t = upper*8 + r
    #pragma unroll
    for (int r = 0; r < 8; r++) {
        const int t = (upper ? 8 : 0) + r;
        float* crow = spikes + (size_t)(t * B + b) * N + n0;
        float4 o;
        o.x = sp[r][0];
        o.y = sp[r][1];
        o.z = sp[r][2];
        o.w = sp[r][3];
        *reinterpret_cast<float4*>(crow) = o;
    }
    #undef AS
    #undef WS
}

// ----------------------------- launch --------------------------------------
extern "C" void kernel_launch(void* const* d_in, const int* in_sizes, int n_in,
                              void* d_out, int out_size) {
    const float* x    = (const float*)d_in[0];  // [T*B, F_IN]
    const float* w    = (const float*)d_in[1];  // [F_OUT, F_IN]
    const float* bias = (const float*)d_in[2];  // [F_OUT]

    const int F_OUT = in_sizes[2];                 // 1024
    const int F_IN  = in_sizes[1] / F_OUT;         // 1024
    const int M     = in_sizes[0] / F_IN;          // 32768
    const int B     = M / T_STEPS;                 // 2048

    cudaFuncSetAttribute(spikelinear_fused_kernel,
                         cudaFuncAttributeMaxDynamicSharedMemorySize,
                         SMEM_BYTES);

    dim3 grid(F_OUT / BN, B / (BM / T_STEPS));     // (16, 256)
    spikelinear_fused_kernel<<<grid, 256, SMEM_BYTES>>>(x, w, bias,
                                                        (float*)d_out,
                                                        B, F_OUT, F_IN);
}

// round 10
// speedup vs baseline: 1.2236x; 1.2191x over previous
#include <cuda_runtime.h>
#include <cuda_bf16.h>
#include <cstdint>

// ---------------------------------------------------------------------------
// SpikeLinear: out = x @ W^T + bias, then LIF scan (T=16), fully fused.
//
// Round 10: Round-7 structure (BK=16, proven 1440 us) with a 4-stage shared
// ring and ONE __syncthreads per 2 iterations (32 barriers instead of 64) to
// test the barrier-drain theory in isolation. Stage written at end of iter i
// ((i+2)%4) was last read at iter i-2; syncs after every odd iteration sit
// strictly between every such read/write pair (both parities verified).
//
// Arithmetic bitwise-identical to rounds 4-9 (Eigen kc=248 panel replication
// via fma.rn.f32x2, rel_err 0.000970705): ascending-k fmaf per panel,
// ascending panel folds (k_end = 248/496/744/992/1024), + bias, ascending-t
// LIF scan.
// ---------------------------------------------------------------------------

#define KC 248               // Eigen panel width (validated round 4)

#define BM 128
#define BN 64
#define BK 16
#define TN 4
#define T_STEPS 16

#define STAGE_FLOATS (BK * (BM + BN))          // 3072 floats = 12 KB
#define SMEM_BYTES   (4 * STAGE_FLOATS * 4)    // 48 KB

#define FMA_F32X2(d, a, b, c) \
    asm("fma.rn.f32x2 %0, %1, %2, %3;" : "=l"(d) : "l"(a), "l"(b), "l"(c))
#define ADD_F32X2_(d, a, b) \
    asm("add.rn.f32x2 %0, %1, %2;" : "=l"(d) : "l"(a), "l"(b))
#define PACK_DUP_F32(d, x) \
    asm("mov.b64 %0, {%1, %2};" : "=l"(d) : "f"(x), "f"(x))
#define UNPACK_F32X2_(lo, hi, p) \
    asm("mov.b64 {%0, %1}, %2;" : "=f"(lo), "=f"(hi) : "l"(p))

__global__ __launch_bounds__(256, 2)
void spikelinear_fused_kernel(const float* __restrict__ A,
                              const float* __restrict__ W,
                              const float* __restrict__ bias,
                              float* __restrict__ spikes,
                              int B, int N, int K) {
    extern __shared__ float smem[];
    // stage s: As = smem + s*STAGE_FLOATS            ([BK][BM])
    //          Ws = smem + s*STAGE_FLOATS + BK*BM    ([BK][BN])
    float* const st0 = smem + 0 * STAGE_FLOATS;
    float* const st1 = smem + 1 * STAGE_FLOATS;
    float* const st2 = smem + 2 * STAGE_FLOATS;
    float* const st3 = smem + 3 * STAGE_FLOATS;

    const int tid    = threadIdx.x;          // 0..255
    const int b_tile = blockIdx.y;            // batch tile (8 b's)
    const int bcol   = blockIdx.x;            // N tile

    const int tcol = tid % (BN / TN);          // 0..15
    const int trow = tid / (BN / TN);          // 0..15

    const int b_base = b_tile * (BM / T_STEPS);   // 8 b's per block

    // packed accumulators: [m-pair 0..3][n 0..3]
    unsigned long long cur[4][TN];
    unsigned long long tot[4][TN];
    #pragma unroll
    for (int i = 0; i < 4; i++)
        #pragma unroll
        for (int j = 0; j < TN; j++) { cur[i][j] = 0ull; tot[i][j] = 0ull; }

    const float* Wb = W + (size_t)bcol * BN * K;

    // loader mapping (BK=16): A tile 128x16 -> 2 float4/thread,
    // W tile 64x16 -> 1 float4/thread.
    const int ld_row = tid / 4;               // 0..63
    const int ld_col = (tid % 4) * 4;         // 0,4,8,12

    // tile_row -> global m: b_local = row>>4, t = row&15, m = t*B + b_base + b_local
    const int tr0 = ld_row;
    const int tr1 = ld_row + 64;
    const float* rowA0 = A + (size_t)((tr0 & 15) * B + b_base + (tr0 >> 4)) * K;
    const float* rowA1 = A + (size_t)((tr1 & 15) * B + b_base + (tr1 >> 4)) * K;
    const float* rowW  = Wb + (size_t)ld_row * K;

    float4 rA0, rA1, rW;

    // STS of the register-held tile into stage S
#define STS_TILE(S)                                                         \
    {                                                                       \
        float* as_ = (S);                                                   \
        float* ws_ = (S) + BK * BM;                                         \
        as_[(ld_col + 0) * BM + tr0] = rA0.x;                               \
        as_[(ld_col + 1) * BM + tr0] = rA0.y;                               \
        as_[(ld_col + 2) * BM + tr0] = rA0.z;                               \
        as_[(ld_col + 3) * BM + tr0] = rA0.w;                               \
        as_[(ld_col + 0) * BM + tr1] = rA1.x;                               \
        as_[(ld_col + 1) * BM + tr1] = rA1.y;                               \
        as_[(ld_col + 2) * BM + tr1] = rA1.z;                               \
        as_[(ld_col + 3) * BM + tr1] = rA1.w;                               \
        ws_[(ld_col + 0) * BN + ld_row] = rW.x;                             \
        ws_[(ld_col + 1) * BN + ld_row] = rW.y;                             \
        ws_[(ld_col + 2) * BN + ld_row] = rW.z;                             \
        ws_[(ld_col + 3) * BN + ld_row] = rW.w;                             \
    }

    // one GEMM iteration: prefetch tile I+2, compute stage CUR, STS -> NXT
#define GEMM_ITER(I, CUR, NXT)                                              \
    {                                                                       \
        const int k0_ = (I) * BK;                                           \
        const bool has_pf_ = (I) + 2 < niter;                               \
        if (has_pf_) {                                                      \
            const int kn_ = ((I) + 2) * BK + ld_col;                        \
            rA0 = *reinterpret_cast<const float4*>(rowA0 + kn_);            \
            rA1 = *reinterpret_cast<const float4*>(rowA1 + kn_);            \
            rW  = *reinterpret_cast<const float4*>(rowW + kn_);             \
        }                                                                   \
        int fold_local_ = -1;                                               \
        {                                                                   \
            int next_b_ = ((k0_ / KC) + 1) * KC;                            \
            if (next_b_ <= k0_ + BK)      fold_local_ = next_b_ - k0_ - 1;  \
            else if (k0_ + BK == K)       fold_local_ = BK - 1;             \
        }                                                                   \
        const float* as_ = (CUR);                                           \
        const float* ws_ = (CUR) + BK * BM;                                 \
        _Pragma("unroll")                                                   \
        for (int k = 0; k < BK; k++) {                                      \
            const ulonglong2* As2_ = reinterpret_cast<const ulonglong2*>(   \
                as_ + k * BM + trow * 8);                                   \
            ulonglong2 al_ = As2_[0];                                       \
            ulonglong2 ah_ = As2_[1];                                       \
            unsigned long long ap_[4] = {al_.x, al_.y, ah_.x, ah_.y};       \
            const float4* Ws4_ =                                            \
                reinterpret_cast<const float4*>(ws_ + k * BN);              \
            float4 w_ = Ws4_[tcol];                                         \
            unsigned long long wp_[TN];                                     \
            PACK_DUP_F32(wp_[0], w_.x);                                     \
            PACK_DUP_F32(wp_[1], w_.y);                                     \
            PACK_DUP_F32(wp_[2], w_.z);                                     \
            PACK_DUP_F32(wp_[3], w_.w);                                     \
            _Pragma("unroll")                                               \
            for (int i = 0; i < 4; i++)                                     \
                _Pragma("unroll")                                           \
                for (int j = 0; j < TN; j++)                                \
                    FMA_F32X2(cur[i][j], ap_[i], wp_[j], cur[i][j]);        \
            if (k == fold_local_) {                                         \
                _Pragma("unroll")                                           \
                for (int i = 0; i < 4; i++)                                 \
                    _Pragma("unroll")                                       \
                    for (int j = 0; j < TN; j++) {                          \
                        ADD_F32X2_(tot[i][j], tot[i][j], cur[i][j]);        \
                        cur[i][j] = 0ull;                                   \
                    }                                                       \
            }                                                               \
        }                                                                   \
        if (has_pf_) STS_TILE(NXT);                                         \
    }

    const int niter = K / BK;   // 64

    // ---- prologue: fill stages 0 and 1 ----
    rA0 = *reinterpret_cast<const float4*>(rowA0 + ld_col);
    rA1 = *reinterpret_cast<const float4*>(rowA1 + ld_col);
    rW  = *reinterpret_cast<const float4*>(rowW + ld_col);
    STS_TILE(st0);
    rA0 = *reinterpret_cast<const float4*>(rowA0 + BK + ld_col);
    rA1 = *reinterpret_cast<const float4*>(rowA1 + BK + ld_col);
    rW  = *reinterpret_cast<const float4*>(rowW + BK + ld_col);
    STS_TILE(st1);
    __syncthreads();

    // ---- main loop: 4-stage ring, sync after every odd iteration ----
    for (int i = 0; i < niter; i += 4) {
        GEMM_ITER(i + 0, st0, st2);
        GEMM_ITER(i + 1, st1, st3);
        __syncthreads();
        GEMM_ITER(i + 2, st2, st0);
        GEMM_ITER(i + 3, st3, st1);
        __syncthreads();
    }

    // ------------------------- fused epilogue -------------------------
    // thread rows: tile rows trow*8 + r (r=0..7)
    //   b_local = trow>>1, t = (trow&1)*8 + r
    const int n0 = bcol * BN + tcol * TN;
    const int b  = b_base + (trow >> 1);
    const bool upper = (trow & 1);

    // unpack + bias (identical scalar fp32 add as rounds 4-9)
    float v[8][TN];
    #pragma unroll
    for (int i = 0; i < 4; i++) {
        float lo[TN], hi[TN];
        #pragma unroll
        for (int j = 0; j < TN; j++)
            UNPACK_F32X2_(lo[j], hi[j], tot[i][j]);
        #pragma unroll
        for (int j = 0; j < TN; j++) {
            v[2 * i + 0][j] = lo[j] + bias[n0 + j];
            v[2 * i + 1][j] = hi[j] + bias[n0 + j];
        }
    }

    // LIF scan, ascending t. Pass 1: scan from 0 (valid for lower half).
    float sp[8][TN];
    float fin[TN];
    #pragma unroll
    for (int j = 0; j < TN; j++) {
        float memb = 0.0f;
        #pragma unroll
        for (int r = 0; r < 8; r++) {
            memb += v[r][j];
            float s = (memb > 1.0f) ? 1.0f : 0.0f;
            sp[r][j] = s;
            memb = (s > 0.0f) ? 0.0f : memb;
        }
        fin[j] = memb;
    }
    // hand membrane from lower half (lane l) to upper half (lane l+16)
    #pragma unroll
    for (int j = 0; j < TN; j++)
        fin[j] = __shfl_up_sync(0xffffffffu, fin[j], 16);
    if (upper) {
        #pragma unroll
        for (int j = 0; j < TN; j++) {
            float memb = fin[j];
            #pragma unroll
            for (int r = 0; r < 8; r++) {
                memb += v[r][j];
                float s = (memb > 1.0f) ? 1.0f : 0.0f;
                sp[r][j] = s;
                memb = (s > 0.0f) ? 0.0f : memb;
            }
        }
    }

    // store spikes: row m = t*B + b, t = upper*8 + r
    #pragma unroll
    for (int r = 0; r < 8; r++) {
        const int t = (upper ? 8 : 0) + r;
        float* crow = spikes + (size_t)(t * B + b) * N + n0;
        float4 o;
        o.x = sp[r][0];
        o.y = sp[r][1];
        o.z = sp[r][2];
        o.w = sp[r][3];
        *reinterpret_cast<float4*>(crow) = o;
    }
}

// ----------------------------- launch --------------------------------------
extern "C" void kernel_launch(void* const* d_in, const int* in_sizes, int n_in,
                              void* d_out, int out_size) {
    const float* x    = (const float*)d_in[0];  // [T*B, F_IN]
    const float* w    = (const float*)d_in[1];  // [F_OUT, F_IN]
    const float* bias = (const float*)d_in[2];  // [F_OUT]

    const int F_OUT = in_sizes[2];                 // 1024
    const int F_IN  = in_sizes[1] / F_OUT;         // 1024
    const int M     = in_sizes[0] / F_IN;          // 32768
    const int B     = M / T_STEPS;                 // 2048

    cudaFuncSetAttribute(spikelinear_fused_kernel,
                         cudaFuncAttributeMaxDynamicSharedMemorySize,
                         SMEM_BYTES);

    dim3 grid(F_OUT / BN, B / (BM / T_STEPS));     // (16, 256)
    spikelinear_fused_kernel<<<grid, 256, SMEM_BYTES>>>(x, w, bias,
                                                        (float*)d_out,
                                                        B, F_OUT, F_IN);
}